// round 15
// baseline (speedup 1.0000x reference)
#include <cuda_runtime.h>
#include <cuda_bf16.h>

// RoiAlign: fm (1,256,50,50) f32, proposals (1024,4) f32 -> out (1024,256,7,7) f32
// Reference double-applies SCALE => /256, roi_w/h clamped >= 1, so every sample
// coord is in [0, 3.23]: all boxes read only fm[:, 0:5, 0:5].
// INSTRUCTION-COUNT attack: each thread owns TWO channels (c, c+64) packed in
// f32x2 (Blackwell FFMA2 via PTX fma.rn.f32x2, full fp32 precision). Weights are
// stored pre-packed {w,w} so one LDS.64 serves both channels; the hot patch is
// stored channel-interleaved so one LDS.64 preloads both. 64-thread CTAs,
// GBOX=2 boxes per CTA, grid (512,2) -> single wave at 7 CTAs/SM.
// Runtime-validated per box with a scalar gmem fallback if a patch exceeds [0,4].

#define C_CH  256
#define HH    50
#define WW    50
#define OUTSZ 7
#define SSAMP 14    // OUT * SR
#define SPAN  5     // fixed patch 0..4 per axis
#define BTH   64    // threads; each owns channels (tid, tid+64) of its 128-ch half
#define GBOX  2     // boxes per block

typedef unsigned long long ull;

__device__ __forceinline__ ull mul2(ull a, ull b) {
    ull d; asm("mul.rn.f32x2 %0, %1, %2;" : "=l"(d) : "l"(a), "l"(b)); return d;
}
__device__ __forceinline__ ull fma2(ull a, ull b, ull c) {
    ull d; asm("fma.rn.f32x2 %0, %1, %2, %3;" : "=l"(d) : "l"(a), "l"(b), "l"(c)); return d;
}

__global__ __launch_bounds__(BTH, 7)
void roi_align_kernel(const float* __restrict__ fm,
                      const float* __restrict__ proposals,
                      float* __restrict__ out)
{
    const int tid  = threadIdx.x;
    const int half = blockIdx.y;
    const int n0   = blockIdx.x * GBOX;

    // union buffer: patch [k][slot] (25*128 floats) during setup, then the
    // 128ch x 49 store stage (6272 floats = 25088 B).
    __shared__ __align__(16) float s_buf[128 * 49];
    __shared__ float s_h[GBOX * 2 * SSAMP], s_l[GBOX * 2 * SSAMP];
    __shared__ int   s_a0[GBOX * 2 * SSAMP], s_a1[GBOX * 2 * SSAMP];
    __shared__ ull   sWy_p[GBOX][OUTSZ][SPAN], sWx_p[GBOX][OUTSZ][SPAN];
    __shared__ int   s_ok[GBOX];

    // ---------- cooperative fill: patch layout s_buf[k*128 + slot(ch)],
    // slot(ch) = 2*(ch%64) + ch/64 so LDS.64 at 2*tid yields (ch=tid, ch=tid+64)
    {
        const float* fmh = fm + (size_t)(half * 128) * (HH * WW);
        int q = tid / 25;            // local channel
        int r = tid - q * 25;        // patch element 0..24
        #pragma unroll 1
        for (int j = 0; j < 50; j++) {
            int row  = (r * 205) >> 10;                    // r/5 for r<25
            int slot = (2 * q + (q >> 6)) & 127;
            s_buf[r * 128 + slot] = fmh[q * (HH * WW) + row * 45 + r]; // row*50+(r%5)
            q += 2; r += 14; if (r >= 25) { r -= 25; q += 1; }
        }
    }

    // ---------- per-box axis sample params: GBOX*28 = 56 threads ----------
    if (tid < GBOX * 2 * SSAMP) {
        const int g = tid / (2 * SSAMP);
        const int j = tid % (2 * SSAMP);
        const bool isY = j < SSAMP;
        const int  s   = isY ? j : j - SSAMP;
        float4 p = reinterpret_cast<const float4*>(proposals)[n0 + g];
        const float sc = 0.0625f;
        float x1 = (p.x * sc) * sc, y1v = (p.y * sc) * sc;
        float x2 = (p.z * sc) * sc, y2v = (p.w * sc) * sc;
        float roiw = fmaxf(x2 - x1, 1.0f);
        float roih = fmaxf(y2v - y1v, 1.0f);
        float gg = ((float)s + 0.5f) * 0.5f;              // (s+0.5)/SR
        float v = isY ? (y1v + (roih * (1.0f / 7.0f)) * gg)
                      : (x1  + (roiw * (1.0f / 7.0f)) * gg);
        const int L = HH;                                  // H == W == 50
        bool valid = (v >= -1.0f) && (v <= (float)L);
        float vc = fminf(fmaxf(v, 0.0f), (float)(L - 1));
        int i0 = min((int)floorf(vc), L - 1);
        int i1 = min(i0 + 1, L - 1);
        float l = vc - (float)i0;
        float h = 1.0f - l;
        if (!valid) { h = 0.0f; l = 0.0f; }
        s_a0[tid] = i0; s_a1[tid] = i1; s_h[tid] = h; s_l[tid] = l;
    }
    __syncthreads();                                       // B1

    // ---------- preload packed channel pair; build packed weights ----------
    ull rp[25];
    #pragma unroll
    for (int k = 0; k < 25; k++)
        rp[k] = *reinterpret_cast<const ull*>(&s_buf[k * 128 + 2 * tid]);

    if (tid < GBOX * 2 * OUTSZ) {          // 28 threads build packed Wy/Wx
        const int g = tid / (2 * OUTSZ);
        const int j = tid % (2 * OUTSZ);
        const bool isY = j < OUTSZ;
        const int  o   = isY ? j : j - OUTSZ;
        const int  off = g * 2 * SSAMP + (isY ? 0 : SSAMP);
        float w[SPAN] = {0.f, 0.f, 0.f, 0.f, 0.f};
        #pragma unroll
        for (int k = 0; k < 2; k++) {
            int s = off + 2 * o + k;
            w[min(s_a0[s], SPAN - 1)] += 0.5f * s_h[s];
            w[min(s_a1[s], SPAN - 1)] += 0.5f * s_l[s];
        }
        #pragma unroll
        for (int q2 = 0; q2 < SPAN; q2++) {
            ull wp = (ull)__float_as_uint(w[q2]);
            wp |= wp << 32;
            if (isY) sWy_p[g][o][q2] = wp; else sWx_p[g][o][q2] = wp;
        }
    } else if (tid >= 28 && tid < 28 + GBOX) {
        const int g = tid - 28;
        int mx = -1;
        #pragma unroll
        for (int s = 0; s < 2 * SSAMP; s++)
            mx = max(mx, s_a1[g * 2 * SSAMP + s]);
        s_ok[g] = (mx <= SPAN - 1) ? 1 : 0;
    }
    __syncthreads();                                       // B2

    const int c0 = half * 128 + tid;          // first channel of this thread
    // (second channel is c0 + 64)

    #pragma unroll 1
    for (int g = 0; g < GBOX; g++) {
        const int n_g = n0 + g;
        if (s_ok[g]) {
            // ---- phase 1: tx[ox][y] = sum_x rp[y][x] * Wx[ox][x]  (packed) ----
            ull tx[OUTSZ][SPAN];
            #pragma unroll
            for (int ox = 0; ox < OUTSZ; ox++) {
                ull w0 = sWx_p[g][ox][0], w1 = sWx_p[g][ox][1], w2 = sWx_p[g][ox][2];
                ull w3 = sWx_p[g][ox][3], w4 = sWx_p[g][ox][4];
                #pragma unroll
                for (int y = 0; y < SPAN; y++) {
                    ull t = mul2(rp[y*5+0], w0);
                    t = fma2(rp[y*5+1], w1, t);
                    t = fma2(rp[y*5+2], w2, t);
                    t = fma2(rp[y*5+3], w3, t);
                    t = fma2(rp[y*5+4], w4, t);
                    tx[ox][y] = t;
                }
            }
            // ---- phase 2: contract y, split halves into the stage ----
            #pragma unroll
            for (int oy = 0; oy < OUTSZ; oy++) {
                ull w0 = sWy_p[g][oy][0], w1 = sWy_p[g][oy][1], w2 = sWy_p[g][oy][2];
                ull w3 = sWy_p[g][oy][3], w4 = sWy_p[g][oy][4];
                #pragma unroll
                for (int ox = 0; ox < OUTSZ; ox++) {
                    ull t = mul2(tx[ox][0], w0);
                    t = fma2(tx[ox][1], w1, t);
                    t = fma2(tx[ox][2], w2, t);
                    t = fma2(tx[ox][3], w3, t);
                    t = fma2(tx[ox][4], w4, t);
                    int p = oy * 7 + ox;
                    s_buf[tid * 49 + p]        = __uint_as_float((unsigned)t);
                    s_buf[(tid + 64) * 49 + p] = __uint_as_float((unsigned)(t >> 32));
                }
            }
        } else {
            // ---------- scalar gmem fallback for both channels ----------
            const int off = g * 2 * SSAMP;
            #pragma unroll 1
            for (int cc = 0; cc < 2; cc++) {
                const int c = c0 + cc * 64;
                const float* fmc = fm + (size_t)c * (HH * WW);
                float* outc = out + ((size_t)n_g * C_CH + c) * 49;
                for (int oy = 0; oy < OUTSZ; oy++) {
                    for (int ox = 0; ox < OUTSZ; ox++) {
                        float a = 0.0f;
                        #pragma unroll
                        for (int ky = 0; ky < 2; ky++) {
                            int sy = off + 2 * oy + ky;
                            int y0 = s_a0[sy] * WW, y1i = s_a1[sy] * WW;
                            float hy = s_h[sy], ly = s_l[sy];
                            #pragma unroll
                            for (int kx = 0; kx < 2; kx++) {
                                int sxi = off + SSAMP + 2 * ox + kx;
                                int x0 = s_a0[sxi], x1i = s_a1[sxi];
                                float hx = s_h[sxi], lx = s_l[sxi];
                                a += hy * (hx * fmc[y0 + x0]  + lx * fmc[y0 + x1i])
                                   + ly * (hx * fmc[y1i + x0] + lx * fmc[y1i + x1i]);
                            }
                        }
                        outc[oy * 7 + ox] = a * 0.25f;
                    }
                }
            }
        }
        __syncthreads();                                   // stage complete

        if (s_ok[g]) {
            // ---- coalesced copy: 1568 float4 = 24*64 + 32 ----
            float4* dst = reinterpret_cast<float4*>(
                out + (size_t)n_g * (C_CH * 49) + (size_t)half * (128 * 49));
            const float4* src = reinterpret_cast<const float4*>(s_buf);
            #pragma unroll 4
            for (int it = 0; it < 24; it++)
                dst[it * BTH + tid] = src[it * BTH + tid];
            if (tid < 32)
                dst[24 * BTH + tid] = src[24 * BTH + tid];
        }
        __syncthreads();                                   // stage reusable
    }
}

extern "C" void kernel_launch(void* const* d_in, const int* in_sizes, int n_in,
                              void* d_out, int out_size) {
    const float* fm    = (const float*)d_in[0];   // (1,256,50,50) f32
    const float* props = (const float*)d_in[1];   // (1024,4) f32
    float* out         = (float*)d_out;           // (1024,256,7,7) f32
    int N = in_sizes[1] / 4;
    dim3 grid(N / GBOX, 2);
    roi_align_kernel<<<grid, BTH>>>(fm, props, out);
}